// round 10
// baseline (speedup 1.0000x reference)
#include <cuda_runtime.h>
#include <cuda_fp16.h>
#include <cstdint>

// ---------------------------------------------------------------------------
// Problem constants
// ---------------------------------------------------------------------------
#define NN 50000
#define EE 400000
#define K1 4
#define HH 256
#define NJ 1024                 // K1 * HH
#define DD 1280
#define KK 1280
#define KTILES 20               // KK / 64
#define MTILES 391              // ceil(50000 / 128)
#define MPAD (MTILES * 128)
#define NE (K1 * EE)            // 1.6M edges
#define NB (2 * NN)             // hop-pair buckets: (k>>1, d)
#define NSB 98                  // scan blocks: ceil(NB / 1024)
#define PACKA_WORK (NN * (DD / 4))

// GEMM tiling
#define BM 128
#define BN 128
#define BK 64
#define STAGE_BYTES 32768
#define NSTAGES 3
#define SMEM_TOTAL (NSTAGES * STAGE_BYTES)   // 96 KB

// ---------------------------------------------------------------------------
// Device scratch
// ---------------------------------------------------------------------------
__device__ __align__(16) __half g_A[(size_t)MPAD * KK];   // 128 MB
__device__ __align__(16) __half g_B[(size_t)NJ * KK];     // 2.6 MB
__device__ __align__(16) __half g_Y[(size_t)NN * NJ];     // 102 MB
__device__ int   g_cnt[NB];
__device__ int   g_off[NB];
__device__ int   g_cur[NB];
__device__ int   g_blk[NSB];
__device__ int2  g_pcv[NE];     // (precomputed half-offset into g_Y, val bits)

// ---------------------------------------------------------------------------
// PTX helpers
// ---------------------------------------------------------------------------
__device__ __forceinline__ uint32_t smem_u32(const void* p) {
    uint32_t a;
    asm("{ .reg .u64 t; cvta.to.shared.u64 t, %1; cvt.u32.u64 %0, t; }" : "=r"(a) : "l"(p));
    return a;
}
__device__ __forceinline__ void cp16(uint32_t dst, const void* src) {
    asm volatile("cp.async.cg.shared.global [%0], [%1], 16;" :: "r"(dst), "l"(src));
}
#define CP_COMMIT() asm volatile("cp.async.commit_group;" ::: "memory")
#define CP_WAIT1()  asm volatile("cp.async.wait_group 1;" ::: "memory")

__device__ __forceinline__ void ldsm_x4(uint32_t* d, uint32_t addr) {
    asm volatile("ldmatrix.sync.aligned.m8n8.x4.shared.b16 {%0,%1,%2,%3}, [%4];"
                 : "=r"(d[0]), "=r"(d[1]), "=r"(d[2]), "=r"(d[3]) : "r"(addr));
}
__device__ __forceinline__ void mma16816(float* c, const uint32_t* a, const uint32_t* b) {
    asm volatile(
        "mma.sync.aligned.m16n8k16.row.col.f32.f16.f16.f32 "
        "{%0,%1,%2,%3}, {%4,%5,%6,%7}, {%8,%9}, {%0,%1,%2,%3};"
        : "+f"(c[0]), "+f"(c[1]), "+f"(c[2]), "+f"(c[3])
        : "r"(a[0]), "r"(a[1]), "r"(a[2]), "r"(a[3]), "r"(b[0]), "r"(b[1]));
}

// ---------------------------------------------------------------------------
// Pack A: X fp32 -> g_A fp16
// ---------------------------------------------------------------------------
__global__ void pack_a_kernel(const float* __restrict__ X) {
    int idx = blockIdx.x * blockDim.x + threadIdx.x;
    if (idx >= PACKA_WORK) return;
    int m = idx / (DD / 4);
    int q = idx % (DD / 4);
    float4 x = reinterpret_cast<const float4*>(X)[(size_t)m * (DD / 4) + q];
    __half2 ha = __halves2half2(__float2half_rn(x.x), __float2half_rn(x.y));
    __half2 hb = __halves2half2(__float2half_rn(x.z), __float2half_rn(x.w));
    uint2 hv;
    hv.x = *reinterpret_cast<uint32_t*>(&ha);
    hv.y = *reinterpret_cast<uint32_t*>(&hb);
    *reinterpret_cast<uint2*>(g_A + (size_t)m * KK + q * 4) = hv;
}

// ---------------------------------------------------------------------------
// Pack B: W fp32 [K1, D, H] -> g_B fp16 [k1*H+h][1280]
// ---------------------------------------------------------------------------
__global__ void pack_b_kernel(const float* __restrict__ W) {
    int idx = blockIdx.x * blockDim.x + threadIdx.x;
    if (idx >= K1 * DD * HH) return;
    int h = idx % HH;
    int d = (idx / HH) % DD;
    int k1 = idx / (HH * DD);
    g_B[(size_t)(k1 * HH + h) * KK + d] = __float2half_rn(W[idx]);
}

// ---------------------------------------------------------------------------
// GEMM N-slice (nt0 = first 128-col tile of the slice), 2 CTAs/SM
// ---------------------------------------------------------------------------
__device__ __forceinline__ void issue_stage(int kc, uint32_t sbase, int mt, int nt, int tid) {
    if (kc < KTILES) {
        int kb = kc * BK;
        uint32_t sA = sbase + (uint32_t)(kc % NSTAGES) * STAGE_BYTES;
        uint32_t sB = sA + 16384;
        const __half* Ab = g_A + (size_t)(mt * BM) * KK + kb;
        const __half* Bb = g_B + (size_t)(nt * BN) * KK + kb;
        #pragma unroll
        for (int i = 0; i < 4; i++) {
            int idx = tid + i * 256;
            int row = idx >> 3;
            int c = idx & 7;
            uint32_t sw = (uint32_t)((c * 16) ^ ((row & 7) << 4));
            cp16(sA + row * 128 + sw, Ab + (size_t)row * KK + c * 8);
            cp16(sB + row * 128 + sw, Bb + (size_t)row * KK + c * 8);
        }
    }
    CP_COMMIT();
}

__global__ __launch_bounds__(256, 2) void gemm_kernel(int nt0) {
    extern __shared__ char smem[];
    uint32_t sbase = smem_u32(smem);
    int tid = threadIdx.x, lane = tid & 31, wid = tid >> 5;
    int nt = nt0 + blockIdx.x, mt = blockIdx.y;
    int wm = wid >> 2, wn = wid & 3;

    float acc[4][4][4];
    #pragma unroll
    for (int i = 0; i < 4; i++)
        #pragma unroll
        for (int j = 0; j < 4; j++)
            #pragma unroll
            for (int r = 0; r < 4; r++) acc[i][j][r] = 0.0f;

    issue_stage(0, sbase, mt, nt, tid);
    issue_stage(1, sbase, mt, nt, tid);

    int a_r = lane & 15, a_g = lane >> 4;
    int b_g = lane >> 3, b_r = lane & 7;
    int b_nrow_base = wn * 32 + (b_g >> 1) * 8 + b_r;
    int b_csel = b_g & 1;

    for (int kc = 0; kc < KTILES; kc++) {
        CP_WAIT1();
        __syncthreads();
        issue_stage(kc + 2, sbase, mt, nt, tid);

        uint32_t sA = sbase + (uint32_t)(kc % NSTAGES) * STAGE_BYTES;
        uint32_t sB = sA + 16384;

        #pragma unroll
        for (int ks = 0; ks < 4; ks++) {
            uint32_t af[4][4], bf[2][4];
            #pragma unroll
            for (int mi = 0; mi < 4; mi++) {
                int row = wm * 64 + mi * 16 + a_r;
                int col16 = ks * 2 + a_g;
                uint32_t addr = sA + row * 128 + (uint32_t)((col16 * 16) ^ ((row & 7) << 4));
                ldsm_x4(af[mi], addr);
            }
            #pragma unroll
            for (int p = 0; p < 2; p++) {
                int nrow = b_nrow_base + p * 16;
                int col16 = ks * 2 + b_csel;
                uint32_t addr = sB + nrow * 128 + (uint32_t)((col16 * 16) ^ ((nrow & 7) << 4));
                ldsm_x4(bf[p], addr);
            }
            #pragma unroll
            for (int mi = 0; mi < 4; mi++)
                #pragma unroll
                for (int ni = 0; ni < 4; ni++)
                    mma16816(acc[mi][ni], af[mi], &bf[ni >> 1][(ni & 1) * 2]);
        }
    }

    int nbase = nt * BN + wn * 32;
    #pragma unroll
    for (int mi = 0; mi < 4; mi++) {
        int row0 = mt * BM + wm * 64 + mi * 16 + (lane >> 2);
        #pragma unroll
        for (int ni = 0; ni < 4; ni++) {
            int col = nbase + ni * 8 + (lane & 3) * 2;
            if (row0 < NN) {
                __half2 h = __halves2half2(__float2half_rn(acc[mi][ni][0]),
                                           __float2half_rn(acc[mi][ni][1]));
                *reinterpret_cast<__half2*>(g_Y + (size_t)row0 * NJ + col) = h;
            }
            if (row0 + 8 < NN) {
                __half2 h = __halves2half2(__float2half_rn(acc[mi][ni][2]),
                                           __float2half_rn(acc[mi][ni][3]));
                *reinterpret_cast<__half2*>(g_Y + (size_t)(row0 + 8) * NJ + col) = h;
            }
        }
    }
}

// ---------------------------------------------------------------------------
// CSR build with hop-pair buckets: bucket = (k>>1)*NN + d
// ---------------------------------------------------------------------------
__global__ void zero_cnt_kernel() {
    int i = blockIdx.x * blockDim.x + threadIdx.x;
    if (i < NB) g_cnt[i] = 0;
}

__global__ void hist_kernel(const int* __restrict__ rows) {
    int gw = blockIdx.x * blockDim.x + threadIdx.x;
    if (gw >= NE) return;
    int bkt = (gw / (2 * EE)) * NN + rows[gw];
    atomicAdd(&g_cnt[bkt], 1);
}

__device__ __forceinline__ int block_scan_exc(int v, int* sw, int tid, int nwarps) {
    int lane = tid & 31, w = tid >> 5;
    int x = v;
    #pragma unroll
    for (int d = 1; d < 32; d <<= 1) {
        int y = __shfl_up_sync(0xFFFFFFFFu, x, d);
        if (lane >= d) x += y;
    }
    if (lane == 31) sw[w] = x;
    __syncthreads();
    if (w == 0) {
        int s = (lane < nwarps) ? sw[lane] : 0;
        #pragma unroll
        for (int d = 1; d < 32; d <<= 1) {
            int y = __shfl_up_sync(0xFFFFFFFFu, s, d);
            if (lane >= d) s += y;
        }
        if (lane < nwarps) sw[lane] = s;
    }
    __syncthreads();
    int woff = (w == 0) ? 0 : sw[w - 1];
    return woff + x - v;
}

__global__ __launch_bounds__(1024) void scan1_kernel() {
    __shared__ int sw[32];
    int tid = threadIdx.x;
    int idx = blockIdx.x * 1024 + tid;
    int v = (idx < NB) ? g_cnt[idx] : 0;
    int e = block_scan_exc(v, sw, tid, 32);
    if (idx < NB) g_off[idx] = e;
    if (tid == 1023) g_blk[blockIdx.x] = e + v;
}

__global__ __launch_bounds__(128) void scan2_kernel() {
    __shared__ int sw[32];
    int tid = threadIdx.x;
    int v = (tid < NSB) ? g_blk[tid] : 0;
    int e = block_scan_exc(v, sw, tid, 4);
    if (tid < NSB) g_blk[tid] = e;
}

__global__ __launch_bounds__(1024) void scan3_kernel() {
    int tid = threadIdx.x;
    int idx = blockIdx.x * 1024 + tid;
    if (idx < NB) {
        int o = g_off[idx] + g_blk[blockIdx.x];
        g_off[idx] = o;
        g_cur[idx] = o;
    }
}

__global__ void scatter_kernel(const int* __restrict__ rows, const int* __restrict__ cols,
                               const float* __restrict__ vals) {
    int gw = blockIdx.x * blockDim.x + threadIdx.x;
    if (gw >= NE) return;
    int k = gw / EE;
    int bkt = (k >> 1) * NN + rows[gw];
    int pos = atomicAdd(&g_cur[bkt], 1);
    int key = cols[gw] * NJ + k * HH;   // direct half-offset into g_Y
    g_pcv[pos] = make_int2(key, __float_as_int(vals[gw]));
}

// ---------------------------------------------------------------------------
// Pull SpMM phase: phase 0 = hops {0,1}, bias init, no PReLU.
//                  phase 1 = hops {2,3}, RMW out, apply PReLU.
// One warp per dest row; MLP-8 gather pipeline.
// ---------------------------------------------------------------------------
__global__ __launch_bounds__(256) void spmm_pull_kernel(int phase,
                                                        const float* __restrict__ b,
                                                        const float* __restrict__ alpha_p,
                                                        float* __restrict__ out) {
    __shared__ float bs[HH];
    int tid = threadIdx.x;
    bs[tid] = b[tid] + b[HH + tid] + b[2 * HH + tid] + b[3 * HH + tid];
    __syncthreads();

    int warp = tid >> 5, lane = tid & 31;
    int d = blockIdx.x * 8 + warp;
    if (d >= NN) return;

    int c0 = lane * 8;
    float* orow = out + (size_t)d * HH + c0;

    float a[8];
    if (phase == 0) {
        #pragma unroll
        for (int j = 0; j < 8; j++) a[j] = bs[c0 + j];
    } else {
        float4 o0 = reinterpret_cast<const float4*>(orow)[0];
        float4 o1 = reinterpret_cast<const float4*>(orow)[1];
        a[0] = o0.x; a[1] = o0.y; a[2] = o0.z; a[3] = o0.w;
        a[4] = o1.x; a[5] = o1.y; a[6] = o1.z; a[7] = o1.w;
    }

    int bkt = phase * NN + d;
    int start = g_off[bkt];
    int cnt = g_cnt[bkt];
    int j = 0;
    // MLP-8 main loop
    for (; j + 8 <= cnt; j += 8) {
        int2 cv[8];
        uint4 y[8];
        #pragma unroll
        for (int q = 0; q < 8; q++) cv[q] = g_pcv[start + j + q];
        #pragma unroll
        for (int q = 0; q < 8; q++)
            y[q] = reinterpret_cast<const uint4*>(g_Y + cv[q].x)[lane];
        #pragma unroll
        for (int q = 0; q < 8; q++) {
            float v = __int_as_float(cv[q].y);
            const __half2* h2 = reinterpret_cast<const __half2*>(&y[q]);
            #pragma unroll
            for (int p = 0; p < 4; p++) {
                float2 f = __half22float2(h2[p]);
                a[2 * p + 0] += v * f.x;
                a[2 * p + 1] += v * f.y;
            }
        }
    }
    // MLP-4 remainder
    for (; j + 4 <= cnt; j += 4) {
        int2 cv[4];
        uint4 y[4];
        #pragma unroll
        for (int q = 0; q < 4; q++) cv[q] = g_pcv[start + j + q];
        #pragma unroll
        for (int q = 0; q < 4; q++)
            y[q] = reinterpret_cast<const uint4*>(g_Y + cv[q].x)[lane];
        #pragma unroll
        for (int q = 0; q < 4; q++) {
            float v = __int_as_float(cv[q].y);
            const __half2* h2 = reinterpret_cast<const __half2*>(&y[q]);
            #pragma unroll
            for (int p = 0; p < 4; p++) {
                float2 f = __half22float2(h2[p]);
                a[2 * p + 0] += v * f.x;
                a[2 * p + 1] += v * f.y;
            }
        }
    }
    // singles
    for (; j < cnt; j++) {
        int2 cv = g_pcv[start + j];
        float v = __int_as_float(cv.y);
        uint4 y = reinterpret_cast<const uint4*>(g_Y + cv.x)[lane];
        const __half2* h2 = reinterpret_cast<const __half2*>(&y);
        #pragma unroll
        for (int p = 0; p < 4; p++) {
            float2 f = __half22float2(h2[p]);
            a[2 * p + 0] += v * f.x;
            a[2 * p + 1] += v * f.y;
        }
    }

    if (phase == 1) {
        float alpha = alpha_p[0];
        #pragma unroll
        for (int jj = 0; jj < 8; jj++)
            a[jj] = a[jj] >= 0.f ? a[jj] : alpha * a[jj];
    }
    reinterpret_cast<float4*>(orow)[0] = make_float4(a[0], a[1], a[2], a[3]);
    reinterpret_cast<float4*>(orow)[1] = make_float4(a[4], a[5], a[6], a[7]);
}

// ---------------------------------------------------------------------------
// kernel_launch — inputs: X, rows, cols, vals, W, b, alpha
// 3-stream capture: s2 = pack_b + CSR; s3 = spmm phase 0 (under gemm slice B).
// ---------------------------------------------------------------------------
static cudaStream_t make_stream() {
    cudaStream_t s;
    cudaStreamCreateWithFlags(&s, cudaStreamNonBlocking);
    return s;
}
static cudaEvent_t make_event() {
    cudaEvent_t e;
    cudaEventCreateWithFlags(&e, cudaEventDisableTiming);
    return e;
}

extern "C" void kernel_launch(void* const* d_in, const int* in_sizes, int n_in,
                              void* d_out, int out_size) {
    const float* X     = (const float*)d_in[0];
    const int*   rows  = (const int*)  d_in[1];
    const int*   cols  = (const int*)  d_in[2];
    const float* vals  = (const float*)d_in[3];
    const float* W     = (const float*)d_in[4];
    const float* b     = (const float*)d_in[5];
    const float* alpha = (const float*)d_in[6];
    float* out = (float*)d_out;

    static cudaStream_t s2 = make_stream();
    static cudaStream_t s3 = make_stream();
    static cudaEvent_t e_fork = make_event();
    static cudaEvent_t e_pb   = make_event();
    static cudaEvent_t e_csr  = make_event();
    static cudaEvent_t e_gA   = make_event();
    static cudaEvent_t e_sA   = make_event();

    cudaFuncSetAttribute(gemm_kernel, cudaFuncAttributeMaxDynamicSharedMemorySize, SMEM_TOTAL);

    // fork side stream: pack_b then CSR build
    cudaEventRecord(e_fork, 0);
    cudaStreamWaitEvent(s2, e_fork, 0);
    pack_b_kernel<<<(K1 * DD * HH + 255) / 256, 256, 0, s2>>>(W);
    cudaEventRecord(e_pb, s2);
    zero_cnt_kernel<<<(NB + 255) / 256, 256, 0, s2>>>();
    hist_kernel<<<(NE + 255) / 256, 256, 0, s2>>>(rows);
    scan1_kernel<<<NSB, 1024, 0, s2>>>();
    scan2_kernel<<<1, 128, 0, s2>>>();
    scan3_kernel<<<NSB, 1024, 0, s2>>>();
    scatter_kernel<<<(NE + 255) / 256, 256, 0, s2>>>(rows, cols, vals);
    cudaEventRecord(e_csr, s2);

    // main stream: pack_a, then GEMM slice A (cols 0-511)
    pack_a_kernel<<<(PACKA_WORK + 255) / 256, 256>>>(X);
    cudaStreamWaitEvent(0, e_pb, 0);
    gemm_kernel<<<dim3(4, MTILES), 256, SMEM_TOTAL>>>(0);
    cudaEventRecord(e_gA, 0);

    // GEMM slice B (cols 512-1023) on main stream
    gemm_kernel<<<dim3(4, MTILES), 256, SMEM_TOTAL>>>(4);

    // spmm phase 0 (hops 0,1) on s3 — overlaps GEMM slice B
    cudaStreamWaitEvent(s3, e_gA, 0);
    cudaStreamWaitEvent(s3, e_csr, 0);
    spmm_pull_kernel<<<(NN + 7) / 8, 256, 0, s3>>>(0, b, alpha, out);
    cudaEventRecord(e_sA, s3);

    // spmm phase 1 (hops 2,3) + PReLU on main stream
    cudaStreamWaitEvent(0, e_sA, 0);
    spmm_pull_kernel<<<(NN + 7) / 8, 256>>>(1, b, alpha, out);
}

// round 11
// speedup vs baseline: 1.0127x; 1.0127x over previous
#include <cuda_runtime.h>
#include <cuda_fp16.h>
#include <cstdint>

// ---------------------------------------------------------------------------
// Problem constants
// ---------------------------------------------------------------------------
#define NN 50000
#define EE 400000
#define K1 4
#define HH 256
#define NJ 1024                 // K1 * HH
#define DD 1280
#define KK 1280
#define KTILES 20               // KK / 64
#define MTILES 391              // ceil(50000 / 128)
#define MPAD (MTILES * 128)
#define NE (K1 * EE)            // 1.6M edges
#define NSB 49                  // scan blocks: ceil(NN / 1024)
#define PACKA_WORK (NN * (DD / 4))

// GEMM tiling
#define BM 128
#define BN 128
#define BK 64
#define STAGE_BYTES 32768
#define NSTAGES 3
#define SMEM_TOTAL (NSTAGES * STAGE_BYTES)   // 96 KB

// ---------------------------------------------------------------------------
// Device scratch
// ---------------------------------------------------------------------------
__device__ __align__(16) __half g_A[(size_t)MPAD * KK];   // 128 MB
__device__ __align__(16) __half g_B[(size_t)NJ * KK];     // 2.6 MB
__device__ __align__(16) __half g_Y[(size_t)NN * NJ];     // 102 MB
__device__ int   g_cnt[NN];
__device__ int   g_off[NN];
__device__ int   g_cur[NN];
__device__ int   g_blk[NSB];
__device__ int2  g_pcv[NE];     // (precomputed half-offset into g_Y, val bits)

// ---------------------------------------------------------------------------
// PTX helpers
// ---------------------------------------------------------------------------
__device__ __forceinline__ uint32_t smem_u32(const void* p) {
    uint32_t a;
    asm("{ .reg .u64 t; cvta.to.shared.u64 t, %1; cvt.u32.u64 %0, t; }" : "=r"(a) : "l"(p));
    return a;
}
__device__ __forceinline__ void cp16(uint32_t dst, const void* src) {
    asm volatile("cp.async.cg.shared.global [%0], [%1], 16;" :: "r"(dst), "l"(src));
}
#define CP_COMMIT() asm volatile("cp.async.commit_group;" ::: "memory")
#define CP_WAIT1()  asm volatile("cp.async.wait_group 1;" ::: "memory")

__device__ __forceinline__ void ldsm_x4(uint32_t* d, uint32_t addr) {
    asm volatile("ldmatrix.sync.aligned.m8n8.x4.shared.b16 {%0,%1,%2,%3}, [%4];"
                 : "=r"(d[0]), "=r"(d[1]), "=r"(d[2]), "=r"(d[3]) : "r"(addr));
}
__device__ __forceinline__ void mma16816(float* c, const uint32_t* a, const uint32_t* b) {
    asm volatile(
        "mma.sync.aligned.m16n8k16.row.col.f32.f16.f16.f32 "
        "{%0,%1,%2,%3}, {%4,%5,%6,%7}, {%8,%9}, {%0,%1,%2,%3};"
        : "+f"(c[0]), "+f"(c[1]), "+f"(c[2]), "+f"(c[3])
        : "r"(a[0]), "r"(a[1]), "r"(a[2]), "r"(a[3]), "r"(b[0]), "r"(b[1]));
}

// ---------------------------------------------------------------------------
// Pack A: X fp32 -> g_A fp16
// ---------------------------------------------------------------------------
__global__ void pack_a_kernel(const float* __restrict__ X) {
    int idx = blockIdx.x * blockDim.x + threadIdx.x;
    if (idx >= PACKA_WORK) return;
    int m = idx / (DD / 4);
    int q = idx % (DD / 4);
    float4 x = reinterpret_cast<const float4*>(X)[(size_t)m * (DD / 4) + q];
    __half2 ha = __halves2half2(__float2half_rn(x.x), __float2half_rn(x.y));
    __half2 hb = __halves2half2(__float2half_rn(x.z), __float2half_rn(x.w));
    uint2 hv;
    hv.x = *reinterpret_cast<uint32_t*>(&ha);
    hv.y = *reinterpret_cast<uint32_t*>(&hb);
    *reinterpret_cast<uint2*>(g_A + (size_t)m * KK + q * 4) = hv;
}

// ---------------------------------------------------------------------------
// Pack B: W fp32 [K1, D, H] -> g_B fp16 [k1*H+h][1280]
// ---------------------------------------------------------------------------
__global__ void pack_b_kernel(const float* __restrict__ W) {
    int idx = blockIdx.x * blockDim.x + threadIdx.x;
    if (idx >= K1 * DD * HH) return;
    int h = idx % HH;
    int d = (idx / HH) % DD;
    int k1 = idx / (HH * DD);
    g_B[(size_t)(k1 * HH + h) * KK + d] = __float2half_rn(W[idx]);
}

// ---------------------------------------------------------------------------
// GEMM (fp16 in, fp32 accum, fp16 out), 2 CTAs/SM — monolithic (R9 topology)
// ---------------------------------------------------------------------------
__device__ __forceinline__ void issue_stage(int kc, uint32_t sbase, int mt, int nt, int tid) {
    if (kc < KTILES) {
        int kb = kc * BK;
        uint32_t sA = sbase + (uint32_t)(kc % NSTAGES) * STAGE_BYTES;
        uint32_t sB = sA + 16384;
        const __half* Ab = g_A + (size_t)(mt * BM) * KK + kb;
        const __half* Bb = g_B + (size_t)(nt * BN) * KK + kb;
        #pragma unroll
        for (int i = 0; i < 4; i++) {
            int idx = tid + i * 256;
            int row = idx >> 3;
            int c = idx & 7;
            uint32_t sw = (uint32_t)((c * 16) ^ ((row & 7) << 4));
            cp16(sA + row * 128 + sw, Ab + (size_t)row * KK + c * 8);
            cp16(sB + row * 128 + sw, Bb + (size_t)row * KK + c * 8);
        }
    }
    CP_COMMIT();
}

__global__ __launch_bounds__(256, 2) void gemm_kernel() {
    extern __shared__ char smem[];
    uint32_t sbase = smem_u32(smem);
    int tid = threadIdx.x, lane = tid & 31, wid = tid >> 5;
    int nt = blockIdx.x, mt = blockIdx.y;
    int wm = wid >> 2, wn = wid & 3;

    float acc[4][4][4];
    #pragma unroll
    for (int i = 0; i < 4; i++)
        #pragma unroll
        for (int j = 0; j < 4; j++)
            #pragma unroll
            for (int r = 0; r < 4; r++) acc[i][j][r] = 0.0f;

    issue_stage(0, sbase, mt, nt, tid);
    issue_stage(1, sbase, mt, nt, tid);

    int a_r = lane & 15, a_g = lane >> 4;
    int b_g = lane >> 3, b_r = lane & 7;
    int b_nrow_base = wn * 32 + (b_g >> 1) * 8 + b_r;
    int b_csel = b_g & 1;

    for (int kc = 0; kc < KTILES; kc++) {
        CP_WAIT1();
        __syncthreads();
        issue_stage(kc + 2, sbase, mt, nt, tid);

        uint32_t sA = sbase + (uint32_t)(kc % NSTAGES) * STAGE_BYTES;
        uint32_t sB = sA + 16384;

        #pragma unroll
        for (int ks = 0; ks < 4; ks++) {
            uint32_t af[4][4], bf[2][4];
            #pragma unroll
            for (int mi = 0; mi < 4; mi++) {
                int row = wm * 64 + mi * 16 + a_r;
                int col16 = ks * 2 + a_g;
                uint32_t addr = sA + row * 128 + (uint32_t)((col16 * 16) ^ ((row & 7) << 4));
                ldsm_x4(af[mi], addr);
            }
            #pragma unroll
            for (int p = 0; p < 2; p++) {
                int nrow = b_nrow_base + p * 16;
                int col16 = ks * 2 + b_csel;
                uint32_t addr = sB + nrow * 128 + (uint32_t)((col16 * 16) ^ ((nrow & 7) << 4));
                ldsm_x4(bf[p], addr);
            }
            #pragma unroll
            for (int mi = 0; mi < 4; mi++)
                #pragma unroll
                for (int ni = 0; ni < 4; ni++)
                    mma16816(acc[mi][ni], af[mi], &bf[ni >> 1][(ni & 1) * 2]);
        }
    }

    int nbase = nt * BN + wn * 32;
    #pragma unroll
    for (int mi = 0; mi < 4; mi++) {
        int row0 = mt * BM + wm * 64 + mi * 16 + (lane >> 2);
        #pragma unroll
        for (int ni = 0; ni < 4; ni++) {
            int col = nbase + ni * 8 + (lane & 3) * 2;
            if (row0 < NN) {
                __half2 h = __halves2half2(__float2half_rn(acc[mi][ni][0]),
                                           __float2half_rn(acc[mi][ni][1]));
                *reinterpret_cast<__half2*>(g_Y + (size_t)row0 * NJ + col) = h;
            }
            if (row0 + 8 < NN) {
                __half2 h = __halves2half2(__float2half_rn(acc[mi][ni][2]),
                                           __float2half_rn(acc[mi][ni][3]));
                *reinterpret_cast<__half2*>(g_Y + (size_t)(row0 + 8) * NJ + col) = h;
            }
        }
    }
}

// ---------------------------------------------------------------------------
// CSR build (d-only buckets): zero -> hist -> scan -> scatter
// Scatter stores the PRECOMPUTED half-element offset into g_Y: col*1024 + k*256
// ---------------------------------------------------------------------------
__global__ void zero_cnt_kernel() {
    int i = blockIdx.x * blockDim.x + threadIdx.x;
    if (i < NN) g_cnt[i] = 0;
}

__global__ void hist_kernel(const int* __restrict__ rows) {
    int gw = blockIdx.x * blockDim.x + threadIdx.x;
    if (gw >= NE) return;
    atomicAdd(&g_cnt[rows[gw]], 1);
}

__device__ __forceinline__ int block_scan_exc(int v, int* sw, int tid, int nwarps) {
    int lane = tid & 31, w = tid >> 5;
    int x = v;
    #pragma unroll
    for (int d = 1; d < 32; d <<= 1) {
        int y = __shfl_up_sync(0xFFFFFFFFu, x, d);
        if (lane >= d) x += y;
    }
    if (lane == 31) sw[w] = x;
    __syncthreads();
    if (w == 0) {
        int s = (lane < nwarps) ? sw[lane] : 0;
        #pragma unroll
        for (int d = 1; d < 32; d <<= 1) {
            int y = __shfl_up_sync(0xFFFFFFFFu, s, d);
            if (lane >= d) s += y;
        }
        if (lane < nwarps) sw[lane] = s;
    }
    __syncthreads();
    int woff = (w == 0) ? 0 : sw[w - 1];
    return woff + x - v;
}

__global__ __launch_bounds__(1024) void scan1_kernel() {
    __shared__ int sw[32];
    int tid = threadIdx.x;
    int idx = blockIdx.x * 1024 + tid;
    int v = (idx < NN) ? g_cnt[idx] : 0;
    int e = block_scan_exc(v, sw, tid, 32);
    if (idx < NN) g_off[idx] = e;
    if (tid == 1023) g_blk[blockIdx.x] = e + v;
}

__global__ __launch_bounds__(64) void scan2_kernel() {
    __shared__ int sw[32];
    int tid = threadIdx.x;
    int v = (tid < NSB) ? g_blk[tid] : 0;
    int e = block_scan_exc(v, sw, tid, 2);
    if (tid < NSB) g_blk[tid] = e;
}

__global__ __launch_bounds__(1024) void scan3_kernel() {
    int tid = threadIdx.x;
    int idx = blockIdx.x * 1024 + tid;
    if (idx < NN) {
        int o = g_off[idx] + g_blk[blockIdx.x];
        g_off[idx] = o;
        g_cur[idx] = o;
    }
}

__global__ void scatter_kernel(const int* __restrict__ rows, const int* __restrict__ cols,
                               const float* __restrict__ vals) {
    int gw = blockIdx.x * blockDim.x + threadIdx.x;
    if (gw >= NE) return;
    int k = gw / EE;
    int pos = atomicAdd(&g_cur[rows[gw]], 1);
    int key = cols[gw] * NJ + k * HH;   // direct half-offset into g_Y
    g_pcv[pos] = make_int2(key, __float_as_int(vals[gw]));
}

// ---------------------------------------------------------------------------
// Pull SpMM (fp16 gathers, fp32 accum): one warp per dest row, MLP-8 pipeline,
// all hops merged per row, fused bias + PReLU, single store.
// ---------------------------------------------------------------------------
__global__ __launch_bounds__(256) void spmm_pull_kernel(const float* __restrict__ b,
                                                        const float* __restrict__ alpha_p,
                                                        float* __restrict__ out) {
    __shared__ float bs[HH];
    int tid = threadIdx.x;
    bs[tid] = b[tid] + b[HH + tid] + b[2 * HH + tid] + b[3 * HH + tid];
    __syncthreads();

    int warp = tid >> 5, lane = tid & 31;
    int d = blockIdx.x * 8 + warp;
    if (d >= NN) return;

    float a[8];
    #pragma unroll
    for (int j = 0; j < 8; j++) a[j] = 0.0f;

    int start = g_off[d];
    int cnt = g_cnt[d];
    int j = 0;
    // MLP-8 main loop
    for (; j + 8 <= cnt; j += 8) {
        int2 cv[8];
        uint4 y[8];
        #pragma unroll
        for (int q = 0; q < 8; q++) cv[q] = g_pcv[start + j + q];
        #pragma unroll
        for (int q = 0; q < 8; q++)
            y[q] = reinterpret_cast<const uint4*>(g_Y + cv[q].x)[lane];
        #pragma unroll
        for (int q = 0; q < 8; q++) {
            float v = __int_as_float(cv[q].y);
            const __half2* h2 = reinterpret_cast<const __half2*>(&y[q]);
            #pragma unroll
            for (int p = 0; p < 4; p++) {
                float2 f = __half22float2(h2[p]);
                a[2 * p + 0] += v * f.x;
                a[2 * p + 1] += v * f.y;
            }
        }
    }
    // MLP-4 remainder
    for (; j + 4 <= cnt; j += 4) {
        int2 cv[4];
        uint4 y[4];
        #pragma unroll
        for (int q = 0; q < 4; q++) cv[q] = g_pcv[start + j + q];
        #pragma unroll
        for (int q = 0; q < 4; q++)
            y[q] = reinterpret_cast<const uint4*>(g_Y + cv[q].x)[lane];
        #pragma unroll
        for (int q = 0; q < 4; q++) {
            float v = __int_as_float(cv[q].y);
            const __half2* h2 = reinterpret_cast<const __half2*>(&y[q]);
            #pragma unroll
            for (int p = 0; p < 4; p++) {
                float2 f = __half22float2(h2[p]);
                a[2 * p + 0] += v * f.x;
                a[2 * p + 1] += v * f.y;
            }
        }
    }
    // singles
    for (; j < cnt; j++) {
        int2 cv = g_pcv[start + j];
        float v = __int_as_float(cv.y);
        uint4 y = reinterpret_cast<const uint4*>(g_Y + cv.x)[lane];
        const __half2* h2 = reinterpret_cast<const __half2*>(&y);
        #pragma unroll
        for (int p = 0; p < 4; p++) {
            float2 f = __half22float2(h2[p]);
            a[2 * p + 0] += v * f.x;
            a[2 * p + 1] += v * f.y;
        }
    }

    float alpha = alpha_p[0];
    int c0 = lane * 8;
    #pragma unroll
    for (int jj = 0; jj < 8; jj++) {
        a[jj] += bs[c0 + jj];
        a[jj] = a[jj] >= 0.f ? a[jj] : alpha * a[jj];
    }
    float4* op = reinterpret_cast<float4*>(out + (size_t)d * HH + c0);
    op[0] = make_float4(a[0], a[1], a[2], a[3]);
    op[1] = make_float4(a[4], a[5], a[6], a[7]);
}

// ---------------------------------------------------------------------------
// kernel_launch — inputs: X, rows, cols, vals, W, b, alpha
// Two-stream capture: s2 = pack_b + CSR build, overlapping pack_a + GEMM.
// ---------------------------------------------------------------------------
static cudaStream_t make_stream() {
    cudaStream_t s;
    cudaStreamCreateWithFlags(&s, cudaStreamNonBlocking);
    return s;
}
static cudaEvent_t make_event() {
    cudaEvent_t e;
    cudaEventCreateWithFlags(&e, cudaEventDisableTiming);
    return e;
}

extern "C" void kernel_launch(void* const* d_in, const int* in_sizes, int n_in,
                              void* d_out, int out_size) {
    const float* X     = (const float*)d_in[0];
    const int*   rows  = (const int*)  d_in[1];
    const int*   cols  = (const int*)  d_in[2];
    const float* vals  = (const float*)d_in[3];
    const float* W     = (const float*)d_in[4];
    const float* b     = (const float*)d_in[5];
    const float* alpha = (const float*)d_in[6];
    float* out = (float*)d_out;

    static cudaStream_t s2 = make_stream();
    static cudaEvent_t e_fork = make_event();
    static cudaEvent_t e_pb   = make_event();
    static cudaEvent_t e_csr  = make_event();

    cudaFuncSetAttribute(gemm_kernel, cudaFuncAttributeMaxDynamicSharedMemorySize, SMEM_TOTAL);

    // fork side stream: pack_b, then CSR build
    cudaEventRecord(e_fork, 0);
    cudaStreamWaitEvent(s2, e_fork, 0);
    pack_b_kernel<<<(K1 * DD * HH + 255) / 256, 256, 0, s2>>>(W);
    cudaEventRecord(e_pb, s2);
    zero_cnt_kernel<<<(NN + 255) / 256, 256, 0, s2>>>();
    hist_kernel<<<(NE + 255) / 256, 256, 0, s2>>>(rows);
    scan1_kernel<<<NSB, 1024, 0, s2>>>();
    scan2_kernel<<<1, 64, 0, s2>>>();
    scan3_kernel<<<NSB, 1024, 0, s2>>>();
    scatter_kernel<<<(NE + 255) / 256, 256, 0, s2>>>(rows, cols, vals);
    cudaEventRecord(e_csr, s2);

    // main stream: pack_a, then monolithic GEMM (needs pack_b)
    pack_a_kernel<<<(PACKA_WORK + 255) / 256, 256>>>(X);
    cudaStreamWaitEvent(0, e_pb, 0);
    gemm_kernel<<<dim3(NJ / BN, MTILES), 256, SMEM_TOTAL>>>();

    // join CSR, then pull SpMM with fused bias + PReLU
    cudaStreamWaitEvent(0, e_csr, 0);
    spmm_pull_kernel<<<(NN + 7) / 8, 256>>>(b, alpha, out);
}